// round 16
// baseline (speedup 1.0000x reference)
#include <cuda_runtime.h>
#include <cuda_bf16.h>
#include <cuda_fp16.h>
#include <cstdint>

// Problem constants (fixed by the reference)
#define NN_PAD 50176          // 392 * 128, padded node count
#define E_MAX  840000
#define NF 128

// ---------------- static scratch (no allocations allowed) ----------------
__device__ __align__(128) float  g_t1s[(size_t)NN_PAD * 128];  // GEMM1 self half (fp32)
__device__ __align__(128) __half g_t1n[(size_t)NN_PAD * 128];  // GEMM1 neigh half (fp16 messages)
__device__ __align__(128) float  g_t2s[(size_t)NN_PAD * 64];   // layer2 self half (fp32)
__device__ __align__(128) __half g_t2n[(size_t)NN_PAD * 64];   // layer2 neigh half (fp16 messages)
__device__ __align__(128) float g_invdeg[NN_PAD];
__device__ __align__(128) int   g_deg[NN_PAD];     // zero-initialized; scan re-zeroes every call
__device__ __align__(128) int   g_start[NN_PAD];
__device__ __align__(128) int   g_cursor[NN_PAD];  // post-scatter: cursor[i] == row end
__device__ __align__(128) int   g_csr[E_MAX];
__device__ __align__(128) int   g_flags[64];       // zero-initialized; scatter re-zeroes every call
__device__ __align__(128) __nv_bfloat16 g_Bt1hi[256 * 128];   // W1^T (n,k) bf16 hi/lo
__device__ __align__(128) __nv_bfloat16 g_Bt1lo[256 * 128];
__device__ __align__(128) __nv_bfloat16 g_Bt2hi[128 * 128];
__device__ __align__(128) __nv_bfloat16 g_Bt2lo[128 * 128];

__device__ __forceinline__ uint32_t pack_bf2(__nv_bfloat16 a, __nv_bfloat16 b) {
    __nv_bfloat162 t = __halves2bfloat162(a, b);
    return *reinterpret_cast<uint32_t*>(&t);
}

// ---------------- weight prep (both layers, one launch): W^T + bf16 hi/lo split ----------------
__global__ void k_prepW_all(const float* __restrict__ Ws1, const float* __restrict__ Wn1,
                            const float* __restrict__ Ws2, const float* __restrict__ Wn2,
                            __nv_bfloat16* __restrict__ B1hi, __nv_bfloat16* __restrict__ B1lo,
                            __nv_bfloat16* __restrict__ B2hi, __nv_bfloat16* __restrict__ B2lo) {
    int idx = blockIdx.x * blockDim.x + threadIdx.x;
    if (idx < 256 * 128) {
        int n = idx >> 7, k = idx & 127;
        float v = (n < 128) ? Ws1[k * 128 + n] : Wn1[k * 128 + (n - 128)];
        __nv_bfloat16 h = __float2bfloat16(v);
        B1hi[idx] = h;
        B1lo[idx] = __float2bfloat16(v - __bfloat162float(h));
    } else if (idx < 256 * 128 + 128 * 128) {
        int i2 = idx - 256 * 128;
        int n = i2 >> 7, k = i2 & 127;
        float v = (n < 64) ? Ws2[k * 64 + n] : Wn2[k * 64 + (n - 64)];
        __nv_bfloat16 h = __float2bfloat16(v);
        B2hi[i2] = h;
        B2lo[i2] = __float2bfloat16(v - __bfloat162float(h));
    }
}

// ---------------- CSR build: histogram -> fused scan -> scatter (side stream) ----------------
__global__ void k_hist(const int* __restrict__ dst, int* __restrict__ deg, int E) {
    int i = blockIdx.x * blockDim.x + threadIdx.x;
    if (i < E) atomicAdd(deg + __ldg(dst + i), 1);
}

// single-launch scan: per-block inclusive scan + inter-block prefix propagation (grid <= 64 < #SM)
__global__ __launch_bounds__(1024) void k_scan_fused(
    int* __restrict__ deg, int* __restrict__ flags,
    int* __restrict__ start, int* __restrict__ cursor,
    float* __restrict__ invdeg, int Nn)
{
    __shared__ int sh[1024];
    __shared__ int s_prefix;
    int i = blockIdx.x * 1024 + threadIdx.x;
    int v = (i < Nn) ? deg[i] : 0;
    if (i < Nn) deg[i] = 0;                       // restore for next replay
    sh[threadIdx.x] = v;
    __syncthreads();
#pragma unroll
    for (int o = 1; o < 1024; o <<= 1) {
        int t = (threadIdx.x >= o) ? sh[threadIdx.x - o] : 0;
        __syncthreads();
        sh[threadIdx.x] += t;
        __syncthreads();
    }
    int incl = sh[threadIdx.x];
    if (threadIdx.x == 1023) {
        int prefix = 0;
        if (blockIdx.x > 0) {
            int t;
            while ((t = atomicAdd(flags + blockIdx.x - 1, 0)) == 0) {}
            prefix = t - 1;                       // stored value = inclusive prefix + 1
        }
        atomicExch(flags + blockIdx.x, prefix + incl + 1);
        s_prefix = prefix;
    }
    __syncthreads();
    if (i < Nn) {
        int s = s_prefix + incl - v;
        start[i]  = s;
        cursor[i] = s;
        invdeg[i] = 1.0f / fmaxf((float)v, 1.0f);
    }
}

__global__ void k_scatter(const int* __restrict__ src, const int* __restrict__ dst,
                          int* __restrict__ cursor, int* __restrict__ csr,
                          int* __restrict__ flags, int E) {
    int i = blockIdx.x * blockDim.x + threadIdx.x;
    if (i < 64) flags[i] = 0;                     // restore for next replay
    if (i < E) {
        int p = atomicAdd(cursor + __ldg(dst + i), 1);
        csr[p] = __ldg(src + i);
    }
}

// ---------------- mma helper ----------------
__device__ __forceinline__ void mma_bf16(float* d, const uint32_t* a, const uint32_t* b) {
    asm volatile(
        "mma.sync.aligned.m16n8k16.row.col.f32.bf16.bf16.f32 "
        "{%0,%1,%2,%3}, {%4,%5,%6,%7}, {%8,%9}, {%0,%1,%2,%3};"
        : "+f"(d[0]), "+f"(d[1]), "+f"(d[2]), "+f"(d[3])
        : "r"(a[0]), "r"(a[1]), "r"(a[2]), "r"(a[3]), "r"(b[0]), "r"(b[1]));
}

#define SMEM_STRIDE 72   // bf16 per row (64 data + 8 pad), GEMM1

__device__ __forceinline__ uint32_t lds_pair_s(const __nv_bfloat16* s, int r, int c, int stride) {
    return *reinterpret_cast<const uint32_t*>(s + r * stride + c);
}

// ---------------- GEMM1: [t1s fp32 | t1n fp16] = x[M,128] @ Bt1[256,128]^T ----------------
// BM=128, BN=128, BK=64, 256 threads = 8 warps 2(M)x4(N), warp tile 64x32.
__global__ __launch_bounds__(256, 2) void gemm_bf16x3(
    const float* __restrict__ A32,
    const __nv_bfloat16* __restrict__ Bhi_g, const __nv_bfloat16* __restrict__ Blo_g,
    float* __restrict__ Cself, __half* __restrict__ Cn, int M, int N, int ncut)
{
    extern __shared__ __nv_bfloat16 smem[];
    __nv_bfloat16* sAhi = smem;                       // 128 x 72
    __nv_bfloat16* sAlo = sAhi + 128 * SMEM_STRIDE;
    __nv_bfloat16* sBhi = sAlo + 128 * SMEM_STRIDE;
    __nv_bfloat16* sBlo = sBhi + 128 * SMEM_STRIDE;

    const int tid  = threadIdx.x;
    const int warp = tid >> 5;
    const int lane = tid & 31;
    const int g    = lane >> 2;
    const int tig  = lane & 3;
    const int wm   = warp & 1;
    const int wn   = warp >> 1;
    const int bm   = blockIdx.y * 128;
    const int bnb  = blockIdx.x * 128;

    float acc[4][4][4];
#pragma unroll
    for (int mi = 0; mi < 4; mi++)
#pragma unroll
        for (int ni = 0; ni < 4; ni++)
#pragma unroll
            for (int f = 0; f < 4; f++) acc[mi][ni][f] = 0.f;

    for (int kk = 0; kk < 128; kk += 64) {
        if (kk) __syncthreads();

#pragma unroll
        for (int i = 0; i < 8; i++) {
            int idx = tid + i * 256;
            int r = idx >> 4, c4 = (idx & 15) * 4;
            float4 v = make_float4(0.f, 0.f, 0.f, 0.f);
            if (bm + r < M)
                v = *reinterpret_cast<const float4*>(A32 + (size_t)(bm + r) * 128 + kk + c4);
            __nv_bfloat16 hx = __float2bfloat16(v.x), hy = __float2bfloat16(v.y);
            __nv_bfloat16 hz = __float2bfloat16(v.z), hw = __float2bfloat16(v.w);
            __nv_bfloat16 lx = __float2bfloat16(v.x - __bfloat162float(hx));
            __nv_bfloat16 ly = __float2bfloat16(v.y - __bfloat162float(hy));
            __nv_bfloat16 lz = __float2bfloat16(v.z - __bfloat162float(hz));
            __nv_bfloat16 lw = __float2bfloat16(v.w - __bfloat162float(hw));
            int o = r * SMEM_STRIDE + c4;
            *reinterpret_cast<uint2*>(sAhi + o) = make_uint2(pack_bf2(hx, hy), pack_bf2(hz, hw));
            *reinterpret_cast<uint2*>(sAlo + o) = make_uint2(pack_bf2(lx, ly), pack_bf2(lz, lw));
        }

#pragma unroll
        for (int i = 0; i < 8; i++) {
            int idx = tid + i * 256;
            int n = idx >> 4, c4 = (idx & 15) * 4;
            int o = n * SMEM_STRIDE + c4;
            *reinterpret_cast<uint2*>(sBhi + o) =
                *reinterpret_cast<const uint2*>(Bhi_g + (size_t)(bnb + n) * 128 + kk + c4);
            *reinterpret_cast<uint2*>(sBlo + o) =
                *reinterpret_cast<const uint2*>(Blo_g + (size_t)(bnb + n) * 128 + kk + c4);
        }
        __syncthreads();

#pragma unroll
        for (int k16 = 0; k16 < 4; k16++) {
            const int c0 = k16 * 16 + tig * 2;
            uint32_t ah[4][4];
#pragma unroll
            for (int mi = 0; mi < 4; mi++) {
                int r0 = wm * 64 + mi * 16 + g;
                ah[mi][0] = lds_pair_s(sAhi, r0,     c0,     SMEM_STRIDE);
                ah[mi][1] = lds_pair_s(sAhi, r0 + 8, c0,     SMEM_STRIDE);
                ah[mi][2] = lds_pair_s(sAhi, r0,     c0 + 8, SMEM_STRIDE);
                ah[mi][3] = lds_pair_s(sAhi, r0 + 8, c0 + 8, SMEM_STRIDE);
            }
            uint32_t bh[4][2];
#pragma unroll
            for (int ni = 0; ni < 4; ni++) {
                int n0 = wn * 32 + ni * 8 + g;
                bh[ni][0] = lds_pair_s(sBhi, n0, c0,     SMEM_STRIDE);
                bh[ni][1] = lds_pair_s(sBhi, n0, c0 + 8, SMEM_STRIDE);
            }
#pragma unroll
            for (int mi = 0; mi < 4; mi++)
#pragma unroll
                for (int ni = 0; ni < 4; ni++) mma_bf16(acc[mi][ni], ah[mi], bh[ni]);

            uint32_t al[4][4];
#pragma unroll
            for (int mi = 0; mi < 4; mi++) {
                int r0 = wm * 64 + mi * 16 + g;
                al[mi][0] = lds_pair_s(sAlo, r0,     c0,     SMEM_STRIDE);
                al[mi][1] = lds_pair_s(sAlo, r0 + 8, c0,     SMEM_STRIDE);
                al[mi][2] = lds_pair_s(sAlo, r0,     c0 + 8, SMEM_STRIDE);
                al[mi][3] = lds_pair_s(sAlo, r0 + 8, c0 + 8, SMEM_STRIDE);
            }
#pragma unroll
            for (int mi = 0; mi < 4; mi++)
#pragma unroll
                for (int ni = 0; ni < 4; ni++) mma_bf16(acc[mi][ni], al[mi], bh[ni]);

            uint32_t bl[4][2];
#pragma unroll
            for (int ni = 0; ni < 4; ni++) {
                int n0 = wn * 32 + ni * 8 + g;
                bl[ni][0] = lds_pair_s(sBlo, n0, c0,     SMEM_STRIDE);
                bl[ni][1] = lds_pair_s(sBlo, n0, c0 + 8, SMEM_STRIDE);
            }
#pragma unroll
            for (int mi = 0; mi < 4; mi++)
#pragma unroll
                for (int ni = 0; ni < 4; ni++) mma_bf16(acc[mi][ni], ah[mi], bl[ni]);
        }
    }

    const int nw = N - ncut;
#pragma unroll
    for (int mi = 0; mi < 4; mi++) {
#pragma unroll
        for (int ni = 0; ni < 4; ni++) {
            int row = bm + wm * 64 + mi * 16 + g;
            int col = bnb + wn * 32 + ni * 8 + tig * 2;
            if (col < ncut) {
                *reinterpret_cast<float2*>(Cself + (size_t)row * ncut + col) =
                    make_float2(acc[mi][ni][0], acc[mi][ni][1]);
                *reinterpret_cast<float2*>(Cself + (size_t)(row + 8) * ncut + col) =
                    make_float2(acc[mi][ni][2], acc[mi][ni][3]);
            } else {
                int c = col - ncut;
                *reinterpret_cast<__half2*>(Cn + (size_t)row * nw + c) =
                    __floats2half2_rn(acc[mi][ni][0], acc[mi][ni][1]);
                *reinterpret_cast<__half2*>(Cn + (size_t)(row + 8) * nw + c) =
                    __floats2half2_rn(acc[mi][ni][2], acc[mi][ni][3]);
            }
        }
    }
}

// ---------------- fused layer 2: agg1 + combine + GEMM2 in one kernel ----------------
__device__ __forceinline__ void acc_half4(float4& acc, uint2 u) {
    float2 f0 = __half22float2(*reinterpret_cast<__half2*>(&u.x));
    float2 f1 = __half22float2(*reinterpret_cast<__half2*>(&u.y));
    acc.x += f0.x; acc.y += f0.y; acc.z += f1.x; acc.w += f1.y;
}

#define L2_STRIDE 136   // bf16 per row (128 data + 8 pad); 68 words % 32 banks = 4 -> conflict-free

// One CTA = 128 nodes. 512 threads = 16 warps.
// Phase A: fill W2 smem tiles. Phase B: each warp aggregates 8 nodes -> h1 (bf16 hi/lo) into A smem.
// Phase C: 3-pass bf16 mma over resident K=128; epilogue [t2s fp32 | t2n fp16].
__global__ __launch_bounds__(512, 1) void k_layer2(
    const float* __restrict__ t1s, const __half* __restrict__ t1n,
    const int* __restrict__ csr, const int* __restrict__ start, const int* __restrict__ endp,
    const float* __restrict__ invdeg, const float* __restrict__ b1,
    const __nv_bfloat16* __restrict__ Bhi_g, const __nv_bfloat16* __restrict__ Blo_g,
    float* __restrict__ t2s, __half* __restrict__ t2n, int Nn)
{
    extern __shared__ __nv_bfloat16 smem[];
    __nv_bfloat16* sAhi = smem;                        // 128 x 136
    __nv_bfloat16* sAlo = sAhi + 128 * L2_STRIDE;
    __nv_bfloat16* sBhi = sAlo + 128 * L2_STRIDE;
    __nv_bfloat16* sBlo = sBhi + 128 * L2_STRIDE;

    const int tid  = threadIdx.x;
    const int warp = tid >> 5;      // 0..15
    const int lane = tid & 31;
    const int bm   = blockIdx.x * 128;

    // ---- Phase A: B fill (128 n-rows x 128 k), uint2 = 4 bf16 per op ----
#pragma unroll
    for (int i = 0; i < 8; i++) {
        int idx = tid + i * 512;                  // 4096 uint2
        int n = idx >> 5, c4 = (idx & 31) * 4;
        int o = n * L2_STRIDE + c4;
        *reinterpret_cast<uint2*>(sBhi + o) =
            *reinterpret_cast<const uint2*>(Bhi_g + (size_t)n * 128 + c4);
        *reinterpret_cast<uint2*>(sBlo + o) =
            *reinterpret_cast<const uint2*>(Blo_g + (size_t)n * 128 + c4);
    }

    // ---- Phase B: aggregation, 8 nodes per warp; h1 -> A smem (bf16 hi/lo split) ----
    for (int j = 0; j < 8; j++) {
        int r    = warp * 8 + j;                  // local row 0..127
        int node = bm + r;
        float o0 = 0.f, o1 = 0.f, o2 = 0.f, o3 = 0.f;
        if (node < Nn) {
            int s0 = __ldg(start + node);
            int d  = __ldg(endp + node) - s0;
            float4 acc = make_float4(0.f, 0.f, 0.f, 0.f);
            int i = 0;
            for (; i + 4 <= d; i += 4) {
                int n0 = __ldg(csr + s0 + i);
                int n1 = __ldg(csr + s0 + i + 1);
                int n2 = __ldg(csr + s0 + i + 2);
                int n3 = __ldg(csr + s0 + i + 3);
                uint2 u0 = __ldg(reinterpret_cast<const uint2*>(t1n + (size_t)n0 * 128) + lane);
                uint2 u1 = __ldg(reinterpret_cast<const uint2*>(t1n + (size_t)n1 * 128) + lane);
                uint2 u2 = __ldg(reinterpret_cast<const uint2*>(t1n + (size_t)n2 * 128) + lane);
                uint2 u3 = __ldg(reinterpret_cast<const uint2*>(t1n + (size_t)n3 * 128) + lane);
                acc_half4(acc, u0); acc_half4(acc, u1); acc_half4(acc, u2); acc_half4(acc, u3);
            }
            for (; i < d; i++) {
                int n0 = __ldg(csr + s0 + i);
                uint2 u0 = __ldg(reinterpret_cast<const uint2*>(t1n + (size_t)n0 * 128) + lane);
                acc_half4(acc, u0);
            }
            float inv = __ldg(invdeg + node);
            float4 sf = *(reinterpret_cast<const float4*>(t1s + (size_t)node * 128) + lane);
            float4 bb = __ldg(reinterpret_cast<const float4*>(b1) + lane);
            o0 = fmaxf(fmaf(acc.x, inv, sf.x + bb.x), 0.f);
            o1 = fmaxf(fmaf(acc.y, inv, sf.y + bb.y), 0.f);
            o2 = fmaxf(fmaf(acc.z, inv, sf.z + bb.z), 0.f);
            o3 = fmaxf(fmaf(acc.w, inv, sf.w + bb.w), 0.f);
        }
        __nv_bfloat16 h0 = __float2bfloat16(o0), h1v = __float2bfloat16(o1);
        __nv_bfloat16 h2 = __float2bfloat16(o2), h3v = __float2bfloat16(o3);
        __nv_bfloat16 l0 = __float2bfloat16(o0 - __bfloat162float(h0));
        __nv_bfloat16 l1 = __float2bfloat16(o1 - __bfloat162float(h1v));
        __nv_bfloat16 l2 = __float2bfloat16(o2 - __bfloat162float(h2));
        __nv_bfloat16 l3 = __float2bfloat16(o3 - __bfloat162float(h3v));
        int o = r * L2_STRIDE + lane * 4;
        *reinterpret_cast<uint2*>(sAhi + o) = make_uint2(pack_bf2(h0, h1v), pack_bf2(h2, h3v));
        *reinterpret_cast<uint2*>(sAlo + o) = make_uint2(pack_bf2(l0, l1), pack_bf2(l2, l3));
    }
    __syncthreads();

    // ---- Phase C: mma mainloop, 16 warps in 4(M)x4(N), warp tile 32x32 ----
    const int g   = lane >> 2;
    const int tig = lane & 3;
    const int wm  = warp & 3;
    const int wn  = warp >> 2;

    float acc[2][4][4];
#pragma unroll
    for (int mi = 0; mi < 2; mi++)
#pragma unroll
        for (int ni = 0; ni < 4; ni++)
#pragma unroll
            for (int f = 0; f < 4; f++) acc[mi][ni][f] = 0.f;

#pragma unroll
    for (int k16 = 0; k16 < 8; k16++) {
        const int c0 = k16 * 16 + tig * 2;
        uint32_t ah[2][4];
#pragma unroll
        for (int mi = 0; mi < 2; mi++) {
            int r0 = wm * 32 + mi * 16 + g;
            ah[mi][0] = lds_pair_s(sAhi, r0,     c0,     L2_STRIDE);
            ah[mi][1] = lds_pair_s(sAhi, r0 + 8, c0,     L2_STRIDE);
            ah[mi][2] = lds_pair_s(sAhi, r0,     c0 + 8, L2_STRIDE);
            ah[mi][3] = lds_pair_s(sAhi, r0 + 8, c0 + 8, L2_STRIDE);
        }
        uint32_t bh[4][2];
#pragma unroll
        for (int ni = 0; ni < 4; ni++) {
            int n0 = wn * 32 + ni * 8 + g;
            bh[ni][0] = lds_pair_s(sBhi, n0, c0,     L2_STRIDE);
            bh[ni][1] = lds_pair_s(sBhi, n0, c0 + 8, L2_STRIDE);
        }
#pragma unroll
        for (int mi = 0; mi < 2; mi++)
#pragma unroll
            for (int ni = 0; ni < 4; ni++) mma_bf16(acc[mi][ni], ah[mi], bh[ni]);

        uint32_t al[2][4];
#pragma unroll
        for (int mi = 0; mi < 2; mi++) {
            int r0 = wm * 32 + mi * 16 + g;
            al[mi][0] = lds_pair_s(sAlo, r0,     c0,     L2_STRIDE);
            al[mi][1] = lds_pair_s(sAlo, r0 + 8, c0,     L2_STRIDE);
            al[mi][2] = lds_pair_s(sAlo, r0,     c0 + 8, L2_STRIDE);
            al[mi][3] = lds_pair_s(sAlo, r0 + 8, c0 + 8, L2_STRIDE);
        }
#pragma unroll
        for (int mi = 0; mi < 2; mi++)
#pragma unroll
            for (int ni = 0; ni < 4; ni++) mma_bf16(acc[mi][ni], al[mi], bh[ni]);

        uint32_t bl[4][2];
#pragma unroll
        for (int ni = 0; ni < 4; ni++) {
            int n0 = wn * 32 + ni * 8 + g;
            bl[ni][0] = lds_pair_s(sBlo, n0, c0,     L2_STRIDE);
            bl[ni][1] = lds_pair_s(sBlo, n0, c0 + 8, L2_STRIDE);
        }
#pragma unroll
        for (int mi = 0; mi < 2; mi++)
#pragma unroll
            for (int ni = 0; ni < 4; ni++) mma_bf16(acc[mi][ni], ah[mi], bl[ni]);
    }

    // epilogue: cols < 64 -> t2s fp32; cols >= 64 -> t2n fp16
#pragma unroll
    for (int mi = 0; mi < 2; mi++) {
#pragma unroll
        for (int ni = 0; ni < 4; ni++) {
            int row = bm + wm * 32 + mi * 16 + g;
            int col = wn * 32 + ni * 8 + tig * 2;
            if (col < 64) {
                *reinterpret_cast<float2*>(t2s + (size_t)row * 64 + col) =
                    make_float2(acc[mi][ni][0], acc[mi][ni][1]);
                *reinterpret_cast<float2*>(t2s + (size_t)(row + 8) * 64 + col) =
                    make_float2(acc[mi][ni][2], acc[mi][ni][3]);
            } else {
                int c = col - 64;
                *reinterpret_cast<__half2*>(t2n + (size_t)row * 64 + c) =
                    __floats2half2_rn(acc[mi][ni][0], acc[mi][ni][1]);
                *reinterpret_cast<__half2*>(t2n + (size_t)(row + 8) * 64 + c) =
                    __floats2half2_rn(acc[mi][ni][2], acc[mi][ni][3]);
            }
        }
    }
}

// ---------------- layer-2 aggregation: out = t2s + mean(t2n) + b2 ----------------
__global__ __launch_bounds__(256) void k_aggcomb2(
    const float* __restrict__ t2s, const __half* __restrict__ t2n,
    const int* __restrict__ csr, const int* __restrict__ start, const int* __restrict__ endp,
    const float* __restrict__ invdeg, const float* __restrict__ b2,
    float* __restrict__ out, int Nn)
{
    int gtid = blockIdx.x * blockDim.x + threadIdx.x;
    int node = gtid >> 4;
    int l    = threadIdx.x & 15;
    if (node >= Nn) return;
    int s0 = __ldg(start + node);
    int d  = __ldg(endp + node) - s0;

    float4 acc = make_float4(0.f, 0.f, 0.f, 0.f);
    int i = 0;
    for (; i + 4 <= d; i += 4) {
        int n0 = __ldg(csr + s0 + i);
        int n1 = __ldg(csr + s0 + i + 1);
        int n2 = __ldg(csr + s0 + i + 2);
        int n3 = __ldg(csr + s0 + i + 3);
        uint2 u0 = __ldg(reinterpret_cast<const uint2*>(t2n + (size_t)n0 * 64) + l);
        uint2 u1 = __ldg(reinterpret_cast<const uint2*>(t2n + (size_t)n1 * 64) + l);
        uint2 u2 = __ldg(reinterpret_cast<const uint2*>(t2n + (size_t)n2 * 64) + l);
        uint2 u3 = __ldg(reinterpret_cast<const uint2*>(t2n + (size_t)n3 * 64) + l);
        acc_half4(acc, u0); acc_half4(acc, u1); acc_half4(acc, u2); acc_half4(acc, u3);
    }
    for (; i < d; i++) {
        int n0 = __ldg(csr + s0 + i);
        uint2 u0 = __ldg(reinterpret_cast<const uint2*>(t2n + (size_t)n0 * 64) + l);
        acc_half4(acc, u0);
    }

    float inv = __ldg(invdeg + node);
    float4 sf = *(reinterpret_cast<const float4*>(t2s + (size_t)node * 64) + l);
    float4 bb = __ldg(reinterpret_cast<const float4*>(b2) + l);
    float4 o;
    o.x = fmaf(acc.x, inv, sf.x + bb.x);
    o.y = fmaf(acc.y, inv, sf.y + bb.y);
    o.z = fmaf(acc.z, inv, sf.z + bb.z);
    o.w = fmaf(acc.w, inv, sf.w + bb.w);
    *(reinterpret_cast<float4*>(out + (size_t)node * 64) + l) = o;
}

// ---------------- launch ----------------
extern "C" void kernel_launch(void* const* d_in, const int* in_sizes, int n_in,
                              void* d_out, int out_size)
{
    const float* x   = (const float*)d_in[0];
    const float* Ws1 = (const float*)d_in[1];
    const float* Wn1 = (const float*)d_in[2];
    const float* b1  = (const float*)d_in[3];
    const float* Ws2 = (const float*)d_in[4];
    const float* Wn2 = (const float*)d_in[5];
    const float* b2  = (const float*)d_in[6];
    const int*   src = (const int*)d_in[7];
    const int*   dst = (const int*)d_in[8];
    float* out = (float*)d_out;

    int Nn = in_sizes[0] / NF;
    int E  = in_sizes[7];

    float *t1s, *t2s, *invdeg;
    __half *t1n, *t2n;
    __nv_bfloat16 *Bt1hi, *Bt1lo, *Bt2hi, *Bt2lo;
    int *deg, *start, *cursor, *csr, *flags;
    cudaGetSymbolAddress((void**)&t1s,    g_t1s);
    cudaGetSymbolAddress((void**)&t1n,    g_t1n);
    cudaGetSymbolAddress((void**)&t2s,    g_t2s);
    cudaGetSymbolAddress((void**)&t2n,    g_t2n);
    cudaGetSymbolAddress((void**)&invdeg, g_invdeg);
    cudaGetSymbolAddress((void**)&deg,    g_deg);
    cudaGetSymbolAddress((void**)&start,  g_start);
    cudaGetSymbolAddress((void**)&cursor, g_cursor);
    cudaGetSymbolAddress((void**)&csr,    g_csr);
    cudaGetSymbolAddress((void**)&flags,  g_flags);
    cudaGetSymbolAddress((void**)&Bt1hi,  g_Bt1hi);
    cudaGetSymbolAddress((void**)&Bt1lo,  g_Bt1lo);
    cudaGetSymbolAddress((void**)&Bt2hi,  g_Bt2hi);
    cudaGetSymbolAddress((void**)&Bt2lo,  g_Bt2lo);

    const int SMEM1 = 4 * 128 * SMEM_STRIDE * (int)sizeof(__nv_bfloat16);  // 73728
    const int SMEM2 = 4 * 128 * L2_STRIDE * (int)sizeof(__nv_bfloat16);    // 139264
    static bool s_init = false;
    static cudaStream_t s1;
    static cudaEvent_t ev_fork, ev_join;
    if (!s_init) {
        cudaFuncSetAttribute(gemm_bf16x3, cudaFuncAttributeMaxDynamicSharedMemorySize, SMEM1);
        cudaFuncSetAttribute(k_layer2,    cudaFuncAttributeMaxDynamicSharedMemorySize, SMEM2);
        cudaStreamCreateWithFlags(&s1, cudaStreamNonBlocking);
        cudaEventCreateWithFlags(&ev_fork, cudaEventDisableTiming);
        cudaEventCreateWithFlags(&ev_join, cudaEventDisableTiming);
        s_init = true;
    }

    int nblk = (Nn + 1023) / 1024;
    int nmt  = (Nn + 127) / 128;

    // ---- fork: CSR build on side stream, overlapped with weight prep + GEMM1 ----
    cudaEventRecord(ev_fork, 0);
    cudaStreamWaitEvent(s1, ev_fork, 0);

    k_hist<<<(E + 255) / 256, 256, 0, s1>>>(dst, deg, E);
    k_scan_fused<<<nblk, 1024, 0, s1>>>(deg, flags, start, cursor, invdeg, Nn);
    k_scatter<<<(E + 255) / 256, 256, 0, s1>>>(src, dst, cursor, csr, flags, E);
    cudaEventRecord(ev_join, s1);

    // main stream: weight prep + GEMM1 (independent of CSR)
    k_prepW_all<<<(256 * 128 + 128 * 128 + 255) / 256, 256>>>(Ws1, Wn1, Ws2, Wn2,
                                                              Bt1hi, Bt1lo, Bt2hi, Bt2lo);
    gemm_bf16x3<<<dim3(2, nmt), 256, SMEM1>>>(x, Bt1hi, Bt1lo, t1s, t1n, Nn, 256, 128);

    // ---- join: layer 2 needs both GEMM1 output and the CSR ----
    cudaStreamWaitEvent(0, ev_join, 0);

    // fused: agg1 + combine + GEMM2
    k_layer2<<<nmt, 512, SMEM2>>>(t1s, t1n, csr, start, cursor, invdeg, b1,
                                  Bt2hi, Bt2lo, t2s, t2n, Nn);

    k_aggcomb2<<<(Nn * 16 + 255) / 256, 256>>>(t2s, t2n, csr, start, cursor, invdeg, b2, out, Nn);
}

// round 17
// speedup vs baseline: 1.2266x; 1.2266x over previous
#include <cuda_runtime.h>
#include <cuda_bf16.h>
#include <cuda_fp16.h>
#include <cstdint>

// Problem constants (fixed by the reference)
#define NN_PAD 50176          // 392 * 128, padded node count
#define E_MAX  840000
#define NF 128

// ---------------- static scratch (no allocations allowed) ----------------
__device__ __align__(128) float  g_t1s[(size_t)NN_PAD * 128];  // GEMM1 self half (fp32)
__device__ __align__(128) __half g_t1n[(size_t)NN_PAD * 128];  // GEMM1 neigh half (fp16 messages)
__device__ __align__(128) float  g_t2s[(size_t)NN_PAD * 64];   // GEMM2 self half (fp32)
__device__ __align__(128) __half g_t2n[(size_t)NN_PAD * 64];   // GEMM2 neigh half (fp16 messages)
__device__ __align__(128) __nv_bfloat16 g_h1hi[(size_t)NN_PAD * 128];  // h1 bf16 split (padding stays 0)
__device__ __align__(128) __nv_bfloat16 g_h1lo[(size_t)NN_PAD * 128];
__device__ __align__(128) float g_invdeg[NN_PAD];
__device__ __align__(128) int   g_deg[NN_PAD];     // zero-initialized; scan re-zeroes every call
__device__ __align__(128) int   g_start[NN_PAD];
__device__ __align__(128) int   g_cursor[NN_PAD];  // post-scatter: cursor[i] == row end
__device__ __align__(128) int   g_csr[E_MAX];
__device__ __align__(128) int   g_flags[64];       // zero-initialized; scatter re-zeroes every call
__device__ __align__(128) __nv_bfloat16 g_Bt1hi[256 * 128];   // W1^T (n,k) bf16 hi/lo
__device__ __align__(128) __nv_bfloat16 g_Bt1lo[256 * 128];
__device__ __align__(128) __nv_bfloat16 g_Bt2hi[128 * 128];
__device__ __align__(128) __nv_bfloat16 g_Bt2lo[128 * 128];

__device__ __forceinline__ uint32_t pack_bf2(__nv_bfloat16 a, __nv_bfloat16 b) {
    __nv_bfloat162 t = __halves2bfloat162(a, b);
    return *reinterpret_cast<uint32_t*>(&t);
}

// ---------------- weight prep (both layers, one launch): W^T + bf16 hi/lo split ----------------
__global__ void k_prepW_all(const float* __restrict__ Ws1, const float* __restrict__ Wn1,
                            const float* __restrict__ Ws2, const float* __restrict__ Wn2,
                            __nv_bfloat16* __restrict__ B1hi, __nv_bfloat16* __restrict__ B1lo,
                            __nv_bfloat16* __restrict__ B2hi, __nv_bfloat16* __restrict__ B2lo) {
    int idx = blockIdx.x * blockDim.x + threadIdx.x;
    if (idx < 256 * 128) {
        int n = idx >> 7, k = idx & 127;
        float v = (n < 128) ? Ws1[k * 128 + n] : Wn1[k * 128 + (n - 128)];
        __nv_bfloat16 h = __float2bfloat16(v);
        B1hi[idx] = h;
        B1lo[idx] = __float2bfloat16(v - __bfloat162float(h));
    } else if (idx < 256 * 128 + 128 * 128) {
        int i2 = idx - 256 * 128;
        int n = i2 >> 7, k = i2 & 127;
        float v = (n < 64) ? Ws2[k * 64 + n] : Wn2[k * 64 + (n - 64)];
        __nv_bfloat16 h = __float2bfloat16(v);
        B2hi[i2] = h;
        B2lo[i2] = __float2bfloat16(v - __bfloat162float(h));
    }
}

// ---------------- CSR build: histogram -> fused scan -> scatter (side stream) ----------------
__global__ void k_hist(const int* __restrict__ dst, int* __restrict__ deg, int E) {
    int i = blockIdx.x * blockDim.x + threadIdx.x;
    if (i < E) atomicAdd(deg + __ldg(dst + i), 1);
}

// single-launch scan: per-block inclusive scan + inter-block prefix propagation (grid <= 64 < #SM)
__global__ __launch_bounds__(1024) void k_scan_fused(
    int* __restrict__ deg, int* __restrict__ flags,
    int* __restrict__ start, int* __restrict__ cursor,
    float* __restrict__ invdeg, int Nn)
{
    __shared__ int sh[1024];
    __shared__ int s_prefix;
    int i = blockIdx.x * 1024 + threadIdx.x;
    int v = (i < Nn) ? deg[i] : 0;
    if (i < Nn) deg[i] = 0;                       // restore for next replay
    sh[threadIdx.x] = v;
    __syncthreads();
#pragma unroll
    for (int o = 1; o < 1024; o <<= 1) {
        int t = (threadIdx.x >= o) ? sh[threadIdx.x - o] : 0;
        __syncthreads();
        sh[threadIdx.x] += t;
        __syncthreads();
    }
    int incl = sh[threadIdx.x];
    if (threadIdx.x == 1023) {
        int prefix = 0;
        if (blockIdx.x > 0) {
            int t;
            while ((t = atomicAdd(flags + blockIdx.x - 1, 0)) == 0) {}
            prefix = t - 1;                       // stored value = inclusive prefix + 1
        }
        atomicExch(flags + blockIdx.x, prefix + incl + 1);
        s_prefix = prefix;
    }
    __syncthreads();
    if (i < Nn) {
        int s = s_prefix + incl - v;
        start[i]  = s;
        cursor[i] = s;
        invdeg[i] = 1.0f / fmaxf((float)v, 1.0f);
    }
}

__global__ void k_scatter(const int* __restrict__ src, const int* __restrict__ dst,
                          int* __restrict__ cursor, int* __restrict__ csr,
                          int* __restrict__ flags, int E) {
    int i = blockIdx.x * blockDim.x + threadIdx.x;
    if (i < 64) flags[i] = 0;                     // restore for next replay
    if (i < E) {
        int p = atomicAdd(cursor + __ldg(dst + i), 1);
        csr[p] = __ldg(src + i);
    }
}

// ---------------- bf16x3 mma.sync GEMM: [self fp32 | neigh fp16] = A[M,128] @ Bt[N,128]^T ----------------
__device__ __forceinline__ void mma_bf16(float* d, const uint32_t* a, const uint32_t* b) {
    asm volatile(
        "mma.sync.aligned.m16n8k16.row.col.f32.bf16.bf16.f32 "
        "{%0,%1,%2,%3}, {%4,%5,%6,%7}, {%8,%9}, {%0,%1,%2,%3};"
        : "+f"(d[0]), "+f"(d[1]), "+f"(d[2]), "+f"(d[3])
        : "r"(a[0]), "r"(a[1]), "r"(a[2]), "r"(a[3]), "r"(b[0]), "r"(b[1]));
}

#define SMEM_STRIDE 72   // bf16 per row (64 data + 8 pad)

__device__ __forceinline__ uint32_t lds_pair(const __nv_bfloat16* s, int r, int c) {
    return *reinterpret_cast<const uint32_t*>(s + r * SMEM_STRIDE + c);
}

// BM=128, BN=128, BK=64, 256 threads = 8 warps 2(M)x4(N), warp tile 64x32.
// Cols < ncut -> Cself fp32 (stride ncut); cols >= ncut -> Cn fp16 (stride N-ncut).
__global__ __launch_bounds__(256, 2) void gemm_bf16x3(
    const float* __restrict__ A32,
    const __nv_bfloat16* __restrict__ Ahi_g, const __nv_bfloat16* __restrict__ Alo_g,
    const __nv_bfloat16* __restrict__ Bhi_g, const __nv_bfloat16* __restrict__ Blo_g,
    float* __restrict__ Cself, __half* __restrict__ Cn, int M, int N, int ncut)
{
    extern __shared__ __nv_bfloat16 smem[];
    __nv_bfloat16* sAhi = smem;                       // 128 x 72
    __nv_bfloat16* sAlo = sAhi + 128 * SMEM_STRIDE;
    __nv_bfloat16* sBhi = sAlo + 128 * SMEM_STRIDE;
    __nv_bfloat16* sBlo = sBhi + 128 * SMEM_STRIDE;

    const int tid  = threadIdx.x;
    const int warp = tid >> 5;
    const int lane = tid & 31;
    const int g    = lane >> 2;
    const int tig  = lane & 3;
    const int wm   = warp & 1;
    const int wn   = warp >> 1;
    const int bm   = blockIdx.y * 128;
    const int bnb  = blockIdx.x * 128;

    float acc[4][4][4];
#pragma unroll
    for (int mi = 0; mi < 4; mi++)
#pragma unroll
        for (int ni = 0; ni < 4; ni++)
#pragma unroll
            for (int f = 0; f < 4; f++) acc[mi][ni][f] = 0.f;

    for (int kk = 0; kk < 128; kk += 64) {
        if (kk) __syncthreads();

        if (A32 != nullptr) {
#pragma unroll
            for (int i = 0; i < 8; i++) {
                int idx = tid + i * 256;
                int r = idx >> 4, c4 = (idx & 15) * 4;
                float4 v = make_float4(0.f, 0.f, 0.f, 0.f);
                if (bm + r < M)
                    v = *reinterpret_cast<const float4*>(A32 + (size_t)(bm + r) * 128 + kk + c4);
                __nv_bfloat16 hx = __float2bfloat16(v.x), hy = __float2bfloat16(v.y);
                __nv_bfloat16 hz = __float2bfloat16(v.z), hw = __float2bfloat16(v.w);
                __nv_bfloat16 lx = __float2bfloat16(v.x - __bfloat162float(hx));
                __nv_bfloat16 ly = __float2bfloat16(v.y - __bfloat162float(hy));
                __nv_bfloat16 lz = __float2bfloat16(v.z - __bfloat162float(hz));
                __nv_bfloat16 lw = __float2bfloat16(v.w - __bfloat162float(hw));
                int o = r * SMEM_STRIDE + c4;
                *reinterpret_cast<uint2*>(sAhi + o) = make_uint2(pack_bf2(hx, hy), pack_bf2(hz, hw));
                *reinterpret_cast<uint2*>(sAlo + o) = make_uint2(pack_bf2(lx, ly), pack_bf2(lz, lw));
            }
        } else {
#pragma unroll
            for (int i = 0; i < 8; i++) {
                int idx = tid + i * 256;
                int r = idx >> 4, c4 = (idx & 15) * 4;
                int o = r * SMEM_STRIDE + c4;
                *reinterpret_cast<uint2*>(sAhi + o) =
                    *reinterpret_cast<const uint2*>(Ahi_g + (size_t)(bm + r) * 128 + kk + c4);
                *reinterpret_cast<uint2*>(sAlo + o) =
                    *reinterpret_cast<const uint2*>(Alo_g + (size_t)(bm + r) * 128 + kk + c4);
            }
        }

#pragma unroll
        for (int i = 0; i < 8; i++) {
            int idx = tid + i * 256;
            int n = idx >> 4, c4 = (idx & 15) * 4;
            int o = n * SMEM_STRIDE + c4;
            *reinterpret_cast<uint2*>(sBhi + o) =
                *reinterpret_cast<const uint2*>(Bhi_g + (size_t)(bnb + n) * 128 + kk + c4);
            *reinterpret_cast<uint2*>(sBlo + o) =
                *reinterpret_cast<const uint2*>(Blo_g + (size_t)(bnb + n) * 128 + kk + c4);
        }
        __syncthreads();

#pragma unroll
        for (int k16 = 0; k16 < 4; k16++) {
            const int c0 = k16 * 16 + tig * 2;
            uint32_t ah[4][4];
#pragma unroll
            for (int mi = 0; mi < 4; mi++) {
                int r0 = wm * 64 + mi * 16 + g;
                ah[mi][0] = lds_pair(sAhi, r0,     c0);
                ah[mi][1] = lds_pair(sAhi, r0 + 8, c0);
                ah[mi][2] = lds_pair(sAhi, r0,     c0 + 8);
                ah[mi][3] = lds_pair(sAhi, r0 + 8, c0 + 8);
            }
            uint32_t bh[4][2];
#pragma unroll
            for (int ni = 0; ni < 4; ni++) {
                int n0 = wn * 32 + ni * 8 + g;
                bh[ni][0] = lds_pair(sBhi, n0, c0);
                bh[ni][1] = lds_pair(sBhi, n0, c0 + 8);
            }
#pragma unroll
            for (int mi = 0; mi < 4; mi++)
#pragma unroll
                for (int ni = 0; ni < 4; ni++) mma_bf16(acc[mi][ni], ah[mi], bh[ni]);

            uint32_t al[4][4];
#pragma unroll
            for (int mi = 0; mi < 4; mi++) {
                int r0 = wm * 64 + mi * 16 + g;
                al[mi][0] = lds_pair(sAlo, r0,     c0);
                al[mi][1] = lds_pair(sAlo, r0 + 8, c0);
                al[mi][2] = lds_pair(sAlo, r0,     c0 + 8);
                al[mi][3] = lds_pair(sAlo, r0 + 8, c0 + 8);
            }
#pragma unroll
            for (int mi = 0; mi < 4; mi++)
#pragma unroll
                for (int ni = 0; ni < 4; ni++) mma_bf16(acc[mi][ni], al[mi], bh[ni]);

            uint32_t bl[4][2];
#pragma unroll
            for (int ni = 0; ni < 4; ni++) {
                int n0 = wn * 32 + ni * 8 + g;
                bl[ni][0] = lds_pair(sBlo, n0, c0);
                bl[ni][1] = lds_pair(sBlo, n0, c0 + 8);
            }
#pragma unroll
            for (int mi = 0; mi < 4; mi++)
#pragma unroll
                for (int ni = 0; ni < 4; ni++) mma_bf16(acc[mi][ni], ah[mi], bl[ni]);
        }
    }

    const int nw = N - ncut;
#pragma unroll
    for (int mi = 0; mi < 4; mi++) {
#pragma unroll
        for (int ni = 0; ni < 4; ni++) {
            int row = bm + wm * 64 + mi * 16 + g;
            int col = bnb + wn * 32 + ni * 8 + tig * 2;
            if (col < ncut) {
                *reinterpret_cast<float2*>(Cself + (size_t)row * ncut + col) =
                    make_float2(acc[mi][ni][0], acc[mi][ni][1]);
                *reinterpret_cast<float2*>(Cself + (size_t)(row + 8) * ncut + col) =
                    make_float2(acc[mi][ni][2], acc[mi][ni][3]);
            } else {
                int c = col - ncut;
                *reinterpret_cast<__half2*>(Cn + (size_t)row * nw + c) =
                    __floats2half2_rn(acc[mi][ni][0], acc[mi][ni][1]);
                *reinterpret_cast<__half2*>(Cn + (size_t)(row + 8) * nw + c) =
                    __floats2half2_rn(acc[mi][ni][2], acc[mi][ni][3]);
            }
        }
    }
}

// ---------------- fused CSR aggregation + combine ----------------
__device__ __forceinline__ void acc_half4(float4& acc, uint2 u) {
    float2 f0 = __half22float2(*reinterpret_cast<__half2*>(&u.x));
    float2 f1 = __half22float2(*reinterpret_cast<__half2*>(&u.y));
    acc.x += f0.x; acc.y += f0.y; acc.z += f1.x; acc.w += f1.y;
}

// Layer 1 (node range [node0, node1)): warp per node; gathers fp16 messages;
// writes h1 as bf16 hi/lo split.
__global__ __launch_bounds__(256) void k_aggcomb1(
    const float* __restrict__ t1s, const __half* __restrict__ t1n,
    const int* __restrict__ csr, const int* __restrict__ start, const int* __restrict__ endp,
    const float* __restrict__ invdeg, const float* __restrict__ b1,
    __nv_bfloat16* __restrict__ h1hi, __nv_bfloat16* __restrict__ h1lo,
    int node0, int node1)
{
    int node = node0 + ((blockIdx.x * blockDim.x + threadIdx.x) >> 5);
    int lane = threadIdx.x & 31;
    if (node >= node1) return;
    int s0 = __ldg(start + node);
    int d  = __ldg(endp + node) - s0;

    float4 acc = make_float4(0.f, 0.f, 0.f, 0.f);
    int i = 0;
    for (; i + 4 <= d; i += 4) {
        int n0 = __ldg(csr + s0 + i);
        int n1 = __ldg(csr + s0 + i + 1);
        int n2 = __ldg(csr + s0 + i + 2);
        int n3 = __ldg(csr + s0 + i + 3);
        uint2 u0 = __ldg(reinterpret_cast<const uint2*>(t1n + (size_t)n0 * 128) + lane);
        uint2 u1 = __ldg(reinterpret_cast<const uint2*>(t1n + (size_t)n1 * 128) + lane);
        uint2 u2 = __ldg(reinterpret_cast<const uint2*>(t1n + (size_t)n2 * 128) + lane);
        uint2 u3 = __ldg(reinterpret_cast<const uint2*>(t1n + (size_t)n3 * 128) + lane);
        acc_half4(acc, u0); acc_half4(acc, u1); acc_half4(acc, u2); acc_half4(acc, u3);
    }
    for (; i < d; i++) {
        int n0 = __ldg(csr + s0 + i);
        uint2 u0 = __ldg(reinterpret_cast<const uint2*>(t1n + (size_t)n0 * 128) + lane);
        acc_half4(acc, u0);
    }

    float inv = __ldg(invdeg + node);
    float4 sf = *(reinterpret_cast<const float4*>(t1s + (size_t)node * 128) + lane);
    float4 bb = __ldg(reinterpret_cast<const float4*>(b1) + lane);
    float o[4];
    o[0] = fmaxf(fmaf(acc.x, inv, sf.x + bb.x), 0.f);
    o[1] = fmaxf(fmaf(acc.y, inv, sf.y + bb.y), 0.f);
    o[2] = fmaxf(fmaf(acc.z, inv, sf.z + bb.z), 0.f);
    o[3] = fmaxf(fmaf(acc.w, inv, sf.w + bb.w), 0.f);

    uint32_t hi[2], lo[2];
#pragma unroll
    for (int j = 0; j < 2; j++) {
        __nv_bfloat16 ha = __float2bfloat16(o[2 * j]);
        __nv_bfloat16 hb = __float2bfloat16(o[2 * j + 1]);
        __nv_bfloat16 la = __float2bfloat16(o[2 * j] - __bfloat162float(ha));
        __nv_bfloat16 lb = __float2bfloat16(o[2 * j + 1] - __bfloat162float(hb));
        hi[j] = pack_bf2(ha, hb);
        lo[j] = pack_bf2(la, lb);
    }
    *(reinterpret_cast<uint2*>(h1hi + (size_t)node * 128) + lane) = make_uint2(hi[0], hi[1]);
    *(reinterpret_cast<uint2*>(h1lo + (size_t)node * 128) + lane) = make_uint2(lo[0], lo[1]);
}

// Layer 2: half-warp per node; gathers fp16 messages. out = t2s + mean + b2
__global__ __launch_bounds__(256) void k_aggcomb2(
    const float* __restrict__ t2s, const __half* __restrict__ t2n,
    const int* __restrict__ csr, const int* __restrict__ start, const int* __restrict__ endp,
    const float* __restrict__ invdeg, const float* __restrict__ b2,
    float* __restrict__ out, int Nn)
{
    int gtid = blockIdx.x * blockDim.x + threadIdx.x;
    int node = gtid >> 4;
    int l    = threadIdx.x & 15;
    if (node >= Nn) return;
    int s0 = __ldg(start + node);
    int d  = __ldg(endp + node) - s0;

    float4 acc = make_float4(0.f, 0.f, 0.f, 0.f);
    int i = 0;
    for (; i + 4 <= d; i += 4) {
        int n0 = __ldg(csr + s0 + i);
        int n1 = __ldg(csr + s0 + i + 1);
        int n2 = __ldg(csr + s0 + i + 2);
        int n3 = __ldg(csr + s0 + i + 3);
        uint2 u0 = __ldg(reinterpret_cast<const uint2*>(t2n + (size_t)n0 * 64) + l);
        uint2 u1 = __ldg(reinterpret_cast<const uint2*>(t2n + (size_t)n1 * 64) + l);
        uint2 u2 = __ldg(reinterpret_cast<const uint2*>(t2n + (size_t)n2 * 64) + l);
        uint2 u3 = __ldg(reinterpret_cast<const uint2*>(t2n + (size_t)n3 * 64) + l);
        acc_half4(acc, u0); acc_half4(acc, u1); acc_half4(acc, u2); acc_half4(acc, u3);
    }
    for (; i < d; i++) {
        int n0 = __ldg(csr + s0 + i);
        uint2 u0 = __ldg(reinterpret_cast<const uint2*>(t2n + (size_t)n0 * 64) + l);
        acc_half4(acc, u0);
    }

    float inv = __ldg(invdeg + node);
    float4 sf = *(reinterpret_cast<const float4*>(t2s + (size_t)node * 64) + l);
    float4 bb = __ldg(reinterpret_cast<const float4*>(b2) + l);
    float4 o;
    o.x = fmaf(acc.x, inv, sf.x + bb.x);
    o.y = fmaf(acc.y, inv, sf.y + bb.y);
    o.z = fmaf(acc.z, inv, sf.z + bb.z);
    o.w = fmaf(acc.w, inv, sf.w + bb.w);
    *(reinterpret_cast<float4*>(out + (size_t)node * 64) + l) = o;
}

// ---------------- launch ----------------
extern "C" void kernel_launch(void* const* d_in, const int* in_sizes, int n_in,
                              void* d_out, int out_size)
{
    const float* x   = (const float*)d_in[0];
    const float* Ws1 = (const float*)d_in[1];
    const float* Wn1 = (const float*)d_in[2];
    const float* b1  = (const float*)d_in[3];
    const float* Ws2 = (const float*)d_in[4];
    const float* Wn2 = (const float*)d_in[5];
    const float* b2  = (const float*)d_in[6];
    const int*   src = (const int*)d_in[7];
    const int*   dst = (const int*)d_in[8];
    float* out = (float*)d_out;

    int Nn = in_sizes[0] / NF;
    int E  = in_sizes[7];

    float *t1s, *t2s, *invdeg;
    __half *t1n, *t2n;
    __nv_bfloat16 *h1hi, *h1lo, *Bt1hi, *Bt1lo, *Bt2hi, *Bt2lo;
    int *deg, *start, *cursor, *csr, *flags;
    cudaGetSymbolAddress((void**)&t1s,    g_t1s);
    cudaGetSymbolAddress((void**)&t1n,    g_t1n);
    cudaGetSymbolAddress((void**)&t2s,    g_t2s);
    cudaGetSymbolAddress((void**)&t2n,    g_t2n);
    cudaGetSymbolAddress((void**)&h1hi,   g_h1hi);
    cudaGetSymbolAddress((void**)&h1lo,   g_h1lo);
    cudaGetSymbolAddress((void**)&invdeg, g_invdeg);
    cudaGetSymbolAddress((void**)&deg,    g_deg);
    cudaGetSymbolAddress((void**)&start,  g_start);
    cudaGetSymbolAddress((void**)&cursor, g_cursor);
    cudaGetSymbolAddress((void**)&csr,    g_csr);
    cudaGetSymbolAddress((void**)&flags,  g_flags);
    cudaGetSymbolAddress((void**)&Bt1hi,  g_Bt1hi);
    cudaGetSymbolAddress((void**)&Bt1lo,  g_Bt1lo);
    cudaGetSymbolAddress((void**)&Bt2hi,  g_Bt2hi);
    cudaGetSymbolAddress((void**)&Bt2lo,  g_Bt2lo);

    const int SMEM = 4 * 128 * SMEM_STRIDE * (int)sizeof(__nv_bfloat16);   // 73728
    static bool s_init = false;
    static cudaStream_t s1;
    static cudaEvent_t ev_fork, ev_join, ev_a0, ev_g0;
    if (!s_init) {
        cudaFuncSetAttribute(gemm_bf16x3, cudaFuncAttributeMaxDynamicSharedMemorySize, SMEM);
        cudaStreamCreateWithFlags(&s1, cudaStreamNonBlocking);
        cudaEventCreateWithFlags(&ev_fork, cudaEventDisableTiming);
        cudaEventCreateWithFlags(&ev_join, cudaEventDisableTiming);
        cudaEventCreateWithFlags(&ev_a0,   cudaEventDisableTiming);
        cudaEventCreateWithFlags(&ev_g0,   cudaEventDisableTiming);
        s_init = true;
    }

    int nblk = (Nn + 1023) / 1024;
    int nmt  = (Nn + 127) / 128;

    // ---- fork: CSR build on side stream, overlapped with weight prep + GEMM1 ----
    cudaEventRecord(ev_fork, 0);
    cudaStreamWaitEvent(s1, ev_fork, 0);

    k_hist<<<(E + 255) / 256, 256, 0, s1>>>(dst, deg, E);
    k_scan_fused<<<nblk, 1024, 0, s1>>>(deg, flags, start, cursor, invdeg, Nn);
    k_scatter<<<(E + 255) / 256, 256, 0, s1>>>(src, dst, cursor, csr, flags, E);
    cudaEventRecord(ev_join, s1);

    // main stream: weight prep + GEMM1 (independent of CSR)
    k_prepW_all<<<(256 * 128 + 128 * 128 + 255) / 256, 256>>>(Ws1, Wn1, Ws2, Wn2,
                                                              Bt1hi, Bt1lo, Bt2hi, Bt2lo);
    gemm_bf16x3<<<dim3(2, nmt), 256, SMEM>>>(x, nullptr, nullptr, Bt1hi, Bt1lo,
                                             t1s, t1n, Nn, 256, 128);

    // ---- join: aggregation needs both GEMM1 and the CSR ----
    cudaStreamWaitEvent(0, ev_join, 0);

    // ---- chunked agg1 / GEMM2 pipeline (chunk boundary at a 128-multiple) ----
    int c0_tiles = nmt / 2;
    int c0 = c0_tiles * 128;                       // node/row boundary (<= Nn)

    // chunk 0 aggregation (main)
    k_aggcomb1<<<(c0 * 32 + 255) / 256, 256>>>(t1s, t1n, csr, start, cursor, invdeg, b1,
                                               h1hi, h1lo, 0, c0);
    cudaEventRecord(ev_a0, 0);

    // chunk 0 GEMM2 on side stream, overlapped with chunk 1 aggregation on main
    cudaStreamWaitEvent(s1, ev_a0, 0);
    gemm_bf16x3<<<dim3(1, c0_tiles), 256, SMEM, s1>>>(
        nullptr, h1hi, h1lo, Bt2hi, Bt2lo, t2s, t2n, c0, 128, 64);
    cudaEventRecord(ev_g0, s1);

    // chunk 1 aggregation (main)
    k_aggcomb1<<<((Nn - c0) * 32 + 255) / 256, 256>>>(t1s, t1n, csr, start, cursor, invdeg, b1,
                                                      h1hi, h1lo, c0, Nn);
    // chunk 1 GEMM2 (main)
    gemm_bf16x3<<<dim3(1, nmt - c0_tiles), 256, SMEM>>>(
        nullptr, h1hi + (size_t)c0 * 128, h1lo + (size_t)c0 * 128, Bt2hi, Bt2lo,
        t2s + (size_t)c0 * 64, t2n + (size_t)c0 * 64, NN_PAD - c0, 128, 64);

    // final aggregation needs both GEMM2 chunks
    cudaStreamWaitEvent(0, ev_g0, 0);
    k_aggcomb2<<<(Nn * 16 + 255) / 256, 256>>>(t2s, t2n, csr, start, cursor, invdeg, b2, out, Nn);
}